// round 6
// baseline (speedup 1.0000x reference)
#include <cuda_runtime.h>
#include <cuda_bf16.h>
#include <cstdint>

#define N_PTS 6000
#define N_TRI 16000
#define N_MOV 4000
#define N_BND 1500
#define BATCH 16
#define EPSF 1e-8f

// GEMM tiling: C[m=4000,n=16] = Vf[m,k=16000] * D[k,16]
#define CK 64                 // k per iteration
#define NCHUNK (N_TRI / CK)   // 250
#define KS 9                  // k-splits: grid 32 x 9 = 288 blocks ~ 2 waves
#define MTILES 32             // 32 * 128 m-rows

// smem: 3 stages; per stage A (128 rows x 288B pitch) + B (32 rows x 144B pitch)
#define A_PITCH 288
#define B_PITCH 144
#define A_STAGE (128 * A_PITCH)              // 36864
#define B_STAGE (32 * B_PITCH)               // 4608
#define STAGE_SZ (A_STAGE + B_STAGE)         // 41472
#define NSTAGE 3
#define SMEM_BYTES (NSTAGE * STAGE_SZ)       // 124416
#define STAGE_TX (128 * 256 + 32 * 128)      // 36864 bytes per stage fill

// ------------------------- device scratch -------------------------
__device__ double g_volc;
__device__ double g_vol[BATCH];
__device__ int    g_owner1[N_PTS];
__device__ int    g_owner2[N_PTS];
__device__ float  g_pz[BATCH * N_PTS * 3];
__device__ __nv_bfloat16 g_dsp[32 * N_TRI];      // rows 0-15: hi[b], rows 16-31: lo[b]
__device__ float  g_cpart[KS * 4096 * 16];       // [ks][m pad 4096][b]
__device__ float  g_c[BATCH * N_MOV];

// ------------------------- small kernels -------------------------
__global__ void k_init() {
    int i = blockIdx.x * 256 + threadIdx.x;
    if (i < N_PTS) { g_owner1[i] = -1; g_owner2[i] = -1; }
    if (i == 0) g_volc = 0.0;
    if (i < BATCH) g_vol[i] = 0.0;
}

__global__ void k_owners(const int* __restrict__ idx1, const int* __restrict__ idx2) {
    int i = blockIdx.x * 256 + threadIdx.x;
    if (i < N_MOV) atomicMax(&g_owner1[idx1[i]], i);
    if (i < N_BND) atomicMax(&g_owner2[idx2[i]], i);
}

__global__ void k_build(const float* __restrict__ x, const float* __restrict__ y,
                        const float* __restrict__ pz0, float* __restrict__ out) {
    int i = blockIdx.x * 256 + threadIdx.x;
    if (i < BATCH * N_PTS) {
        int b = i / N_PTS, p = i - b * N_PTS;
        float cx = pz0[p * 3 + 0], cy = pz0[p * 3 + 1], cz = pz0[p * 3 + 2];
        int o2 = g_owner2[p];
        if (o2 >= 0) {
            cx = y[b * (2 * N_BND) + o2 * 2 + 0];
            cz = y[b * (2 * N_BND) + o2 * 2 + 1];
        }
        int o1 = g_owner1[p];
        if (o1 >= 0) {
            cx = x[(b * N_MOV + o1) * 3 + 0];
            cy = x[(b * N_MOV + o1) * 3 + 1];
            cz = x[(b * N_MOV + o1) * 3 + 2];
        }
        g_pz[i * 3 + 0] = cx; g_pz[i * 3 + 1] = cy; g_pz[i * 3 + 2] = cz;
    }
    int stride = gridDim.x * 256;
    for (int j = i; j < BATCH * N_MOV * 3; j += stride) out[j] = x[j];
}

__global__ void k_vol(const float* __restrict__ pz0, const int* __restrict__ tri) {
    __shared__ double sred[256];
    int t = blockIdx.x * 256 + threadIdx.x;
    int b = blockIdx.y;
    const float* P = (b < BATCH) ? (g_pz + (size_t)b * N_PTS * 3) : pz0;
    double contrib = 0.0;
    if (t < N_TRI) {
        int p0 = tri[3 * t + 0] * 3, p1 = tri[3 * t + 1] * 3, p2 = tri[3 * t + 2] * 3;
        float x0 = P[p0], y0 = P[p0 + 1], z0 = P[p0 + 2];
        float x1 = P[p1], y1 = P[p1 + 1], z1 = P[p1 + 2];
        float x2 = P[p2], y2 = P[p2 + 1], z2 = P[p2 + 2];
        float det = (y1 - y0) * (z2 - z0) - (z1 - z0) * (y2 - y0);
        contrib = (double)((x0 + x1 + x2) * (det * (1.0f / 6.0f)));
    }
    sred[threadIdx.x] = contrib;
    __syncthreads();
    for (int o = 128; o > 0; o >>= 1) {
        if (threadIdx.x < o) sred[threadIdx.x] += sred[threadIdx.x + o];
        __syncthreads();
    }
    if (threadIdx.x == 0) {
        if (b < BATCH) atomicAdd(&g_vol[b], sred[0]);
        else           atomicAdd(&g_volc, sred[0]);
    }
}

// dets -> bf16 hi/lo planes g_dsp[b][t] (hi) and g_dsp[16+b][t] (lo)
template <int AXIS>
__global__ void k_det(const int* __restrict__ tri) {
    int i = blockIdx.x * 256 + threadIdx.x;
    if (i >= BATCH * N_TRI) return;
    int b = i / N_TRI;
    int t = i - b * N_TRI;
    int p0 = tri[3 * t + 0] * 3, p1 = tri[3 * t + 1] * 3, p2 = tri[3 * t + 2] * 3;
    const float* P = g_pz + (size_t)b * N_PTS * 3;
    float det;
    if (AXIS == 2) {       // coeff_z: (x,y), pivot vertex 2
        float x0 = P[p0], y0 = P[p0 + 1], x1 = P[p1], y1 = P[p1 + 1], x2 = P[p2], y2 = P[p2 + 1];
        det = (x0 - x2) * (y1 - y2) - (y0 - y2) * (x1 - x2);
    } else if (AXIS == 1) { // coeff_y: (x,z), pivot vertex 1
        float x0 = P[p0], z0 = P[p0 + 2], x1 = P[p1], z1 = P[p1 + 2], x2 = P[p2], z2 = P[p2 + 2];
        det = (x0 - x1) * (z2 - z1) - (z0 - z1) * (x2 - x1);
    } else {               // coeff_x: (y,z), pivot vertex 0
        float y0 = P[p0 + 1], z0 = P[p0 + 2], y1 = P[p1 + 1], z1 = P[p1 + 2], y2 = P[p2 + 1], z2 = P[p2 + 2];
        det = (y1 - y0) * (z2 - z0) - (z1 - z0) * (y2 - y0);
    }
    float v = det * (1.0f / 6.0f);
    __nv_bfloat16 h = __float2bfloat16_rn(v);
    __nv_bfloat16 l = __float2bfloat16_rn(v - __bfloat162float(h));
    g_dsp[b * N_TRI + t] = h;
    g_dsp[(16 + b) * N_TRI + t] = l;
}

// ------------------------- helpers -------------------------
__device__ __forceinline__ uint32_t smem_u32(const void* p) {
    return (uint32_t)__cvta_generic_to_shared(p);
}
__device__ __forceinline__ void bulk_g2s(uint32_t dst, const void* src, uint32_t bytes, uint32_t mbar) {
    asm volatile(
        "cp.async.bulk.shared::cluster.global.mbarrier::complete_tx::bytes [%0], [%1], %2, [%3];"
        :: "r"(dst), "l"(src), "r"(bytes), "r"(mbar) : "memory");
}
__device__ __forceinline__ void mbar_wait(uint32_t addr, uint32_t parity) {
    asm volatile(
        "{\n\t.reg .pred P;\n\t"
        "W%=:\n\tmbarrier.try_wait.parity.acquire.cta.shared::cta.b64 P, [%0], %1;\n\t"
        "@!P bra W%=;\n\t}"
        :: "r"(addr), "r"(parity) : "memory");
}
// split float2 -> (hi bf16x2, lo bf16x2); low half = first element
__device__ __forceinline__ void bsplit(float a0, float a1, uint32_t& h, uint32_t& l) {
    asm("cvt.rn.bf16x2.f32 %0, %1, %2;" : "=r"(h) : "f"(a1), "f"(a0));
    float h0 = __uint_as_float(h << 16);
    float h1 = __uint_as_float(h & 0xffff0000u);
    asm("cvt.rn.bf16x2.f32 %0, %1, %2;" : "=r"(l) : "f"(a1 - h1), "f"(a0 - h0));
}
#define MMA16816(C0,C1,C2,C3,A0,A1,A2,A3,B0,B1) \
    asm("mma.sync.aligned.m16n8k16.row.col.f32.bf16.bf16.f32 " \
        "{%0,%1,%2,%3},{%4,%5,%6,%7},{%8,%9},{%0,%1,%2,%3};" \
        : "+f"(C0), "+f"(C1), "+f"(C2), "+f"(C3) \
        : "r"(A0), "r"(A1), "r"(A2), "r"(A3), "r"(B0), "r"(B1))

// ------------------------- GEMM: warp MMA, 3-stage bulk-async pipeline -------------------------
__global__ void __launch_bounds__(256, 1) k_gemm(const float* __restrict__ Vf) {
    extern __shared__ __align__(128) char sm[];
    __shared__ __align__(8) unsigned long long s_mbar[NSTAGE];

    const int tid  = threadIdx.x;
    const int lane = tid & 31;
    const int w    = tid >> 5;
    const int g    = lane >> 2;     // 0..7
    const int tig  = lane & 3;      // 0..3
    const int mbase = blockIdx.x * 128;
    const int ksid  = blockIdx.y;
    const int c0 = (NCHUNK * ksid) / KS;
    const int c1 = (NCHUNK * (ksid + 1)) / KS;

    uint32_t mb[NSTAGE];
#pragma unroll
    for (int s = 0; s < NSTAGE; s++) mb[s] = smem_u32(&s_mbar[s]);
    if (tid == 0) {
#pragma unroll
        for (int s = 0; s < NSTAGE; s++)
            asm volatile("mbarrier.init.shared.b64 [%0], 1;" :: "r"(mb[s]) : "memory");
        asm volatile("fence.proxy.async.shared::cta;" ::: "memory");
    }
    __syncthreads();

    const uint32_t sbase = smem_u32(sm);

    // per-thread load roles
    int arow = mbase + tid; if (arow > N_MOV - 1) arow = N_MOV - 1;   // tid<128: Vf row
    const float* asrc = Vf + (size_t)arow * N_TRI;
    const int drow = tid - 128;                                        // 128..159: D row
    const __nv_bfloat16* dsrc = g_dsp + (size_t)(drow < 0 ? 0 : drow) * N_TRI;

    auto issue = [&](int st, int it) {
        const int t0 = it * CK;
        if (tid == 0)
            asm volatile("mbarrier.arrive.expect_tx.shared.b64 _, [%0], %1;"
                         :: "r"(mb[st]), "r"((uint32_t)STAGE_TX) : "memory");
        if (tid < 128)
            bulk_g2s(sbase + st * STAGE_SZ + tid * A_PITCH, asrc + t0, 256, mb[st]);
        else if (tid < 160)
            bulk_g2s(sbase + st * STAGE_SZ + A_STAGE + drow * B_PITCH, dsrc + t0, 128, mb[st]);
    };

    const int niter = c1 - c0;
#pragma unroll
    for (int s = 0; s < NSTAGE; s++)
        if (s < niter) issue(s, c0 + s);

    float acc[2][4];
#pragma unroll
    for (int nt = 0; nt < 2; nt++)
#pragma unroll
        for (int q = 0; q < 4; q++) acc[nt][q] = 0.f;

    int phase[NSTAGE] = { 0, 0, 0 };
    int st = 0;

    for (int li = 0; li < niter; ++li) {
        mbar_wait(mb[st], phase[st]);
        phase[st] ^= 1;

        const char* A0 = sm + st * STAGE_SZ + (w * 16 + g) * A_PITCH;   // row g of warp's m16
        const char* A8 = A0 + 8 * A_PITCH;                              // row g+8
        const char* B  = sm + st * STAGE_SZ + A_STAGE;

#pragma unroll
        for (int ks = 0; ks < 4; ks++) {
            const int ab = ks * 64 + tig * 8;
            float2 x00 = *reinterpret_cast<const float2*>(A0 + ab);
            float2 x10 = *reinterpret_cast<const float2*>(A8 + ab);
            float2 x01 = *reinterpret_cast<const float2*>(A0 + ab + 32);
            float2 x11 = *reinterpret_cast<const float2*>(A8 + ab + 32);
            uint32_t ah0, al0, ah1, al1, ah2, al2, ah3, al3;
            bsplit(x00.x, x00.y, ah0, al0);
            bsplit(x10.x, x10.y, ah1, al1);
            bsplit(x01.x, x01.y, ah2, al2);
            bsplit(x11.x, x11.y, ah3, al3);

            const int kb = ks * 32 + tig * 4;
            uint32_t bh0a = *reinterpret_cast<const uint32_t*>(B + g * B_PITCH + kb);
            uint32_t bh0b = *reinterpret_cast<const uint32_t*>(B + g * B_PITCH + kb + 16);
            uint32_t bh1a = *reinterpret_cast<const uint32_t*>(B + (8 + g) * B_PITCH + kb);
            uint32_t bh1b = *reinterpret_cast<const uint32_t*>(B + (8 + g) * B_PITCH + kb + 16);
            uint32_t bl0a = *reinterpret_cast<const uint32_t*>(B + (16 + g) * B_PITCH + kb);
            uint32_t bl0b = *reinterpret_cast<const uint32_t*>(B + (16 + g) * B_PITCH + kb + 16);
            uint32_t bl1a = *reinterpret_cast<const uint32_t*>(B + (24 + g) * B_PITCH + kb);
            uint32_t bl1b = *reinterpret_cast<const uint32_t*>(B + (24 + g) * B_PITCH + kb + 16);

            MMA16816(acc[0][0], acc[0][1], acc[0][2], acc[0][3], ah0, ah1, ah2, ah3, bh0a, bh0b);
            MMA16816(acc[0][0], acc[0][1], acc[0][2], acc[0][3], ah0, ah1, ah2, ah3, bl0a, bl0b);
            MMA16816(acc[0][0], acc[0][1], acc[0][2], acc[0][3], al0, al1, al2, al3, bh0a, bh0b);
            MMA16816(acc[1][0], acc[1][1], acc[1][2], acc[1][3], ah0, ah1, ah2, ah3, bh1a, bh1b);
            MMA16816(acc[1][0], acc[1][1], acc[1][2], acc[1][3], ah0, ah1, ah2, ah3, bl1a, bl1b);
            MMA16816(acc[1][0], acc[1][1], acc[1][2], acc[1][3], al0, al1, al2, al3, bh1a, bh1b);
        }

        __syncthreads();                 // all warps done reading stage st
        if (li + NSTAGE < niter) issue(st, c0 + li + NSTAGE);
        st = (st + 1 == NSTAGE) ? 0 : st + 1;
    }

    // epilogue: d0,d1 -> (row g, cols 2*tig, 2*tig+1); d2,d3 -> row g+8
    const int m0 = mbase + w * 16 + g;
    const int m1 = m0 + 8;
#pragma unroll
    for (int nt = 0; nt < 2; nt++) {
        const int n0 = nt * 8 + tig * 2;
        if (m0 < N_MOV)
            *reinterpret_cast<float2*>(&g_cpart[((size_t)ksid * 4096 + m0) * 16 + n0]) =
                make_float2(acc[nt][0], acc[nt][1]);
        if (m1 < N_MOV)
            *reinterpret_cast<float2*>(&g_cpart[((size_t)ksid * 4096 + m1) * 16 + n0]) =
                make_float2(acc[nt][2], acc[nt][3]);
    }
}

// ------------------------- fused: finalize c, scale, update pts & pz -------------------------
__global__ void k_scale_update(const int* __restrict__ idx1, float* __restrict__ out, int axis) {
    __shared__ float red[256];
    __shared__ float s_scale;
    int b = blockIdx.x;
    int tid = threadIdx.x;
    float sq = 0.f;
    for (int m = tid; m < N_MOV; m += 256) {
        float cv = 0.f;
#pragma unroll
        for (int sp = 0; sp < KS; sp++)
            cv += g_cpart[((size_t)sp * 4096 + m) * 16 + b];
        g_c[b * N_MOV + m] = cv;
        sq += cv * cv;
    }
    red[tid] = sq;
    __syncthreads();
    for (int o = 128; o > 0; o >>= 1) {
        if (tid < o) red[tid] += red[tid + o];
        __syncthreads();
    }
    if (tid == 0) {
        float a = (float)((g_volc - g_vol[b]) / 3.0);
        s_scale = a / (red[0] + EPSF);
    }
    __syncthreads();
    const float s = s_scale;
    for (int m = tid; m < N_MOV; m += 256) {
        int i = b * N_MOV + m;
        float nv = out[i * 3 + axis] + g_c[i] * s;
        out[i * 3 + axis] = nv;
        int p = idx1[m];
        if (g_owner1[p] == m) g_pz[((size_t)b * N_PTS + p) * 3 + axis] = nv;
    }
}

// ------------------------- host -------------------------
extern "C" void kernel_launch(void* const* d_in, const int* in_sizes, int n_in,
                              void* d_out, int out_size) {
    const float* x   = (const float*)d_in[0];
    const float* y   = (const float*)d_in[1];
    const float* pz0 = (const float*)d_in[2];
    const float* Vf  = (const float*)d_in[3];
    const int* idx1  = (const int*)d_in[4];
    const int* idx2  = (const int*)d_in[5];
    const int* tri   = (const int*)d_in[6];
    float* out = (float*)d_out;

    static bool attr_set = false;   // idempotent attribute set, not result-affecting state
    if (!attr_set) {
        cudaFuncSetAttribute(k_gemm, cudaFuncAttributeMaxDynamicSharedMemorySize, SMEM_BYTES);
        attr_set = true;
    }

    k_init<<<24, 256>>>();
    k_owners<<<16, 256>>>(idx1, idx2);
    k_build<<<375, 256>>>(x, y, pz0, out);
    k_vol<<<dim3(63, BATCH + 1), 256>>>(pz0, tri);

    k_det<2><<<1000, 256>>>(tri);
    k_gemm<<<dim3(MTILES, KS), 256, SMEM_BYTES>>>(Vf);
    k_scale_update<<<BATCH, 256>>>(idx1, out, 2);

    k_det<1><<<1000, 256>>>(tri);
    k_gemm<<<dim3(MTILES, KS), 256, SMEM_BYTES>>>(Vf);
    k_scale_update<<<BATCH, 256>>>(idx1, out, 1);

    k_det<0><<<1000, 256>>>(tri);
    k_gemm<<<dim3(MTILES, KS), 256, SMEM_BYTES>>>(Vf);
    k_scale_update<<<BATCH, 256>>>(idx1, out, 0);
}

// round 7
// speedup vs baseline: 1.4915x; 1.4915x over previous
#include <cuda_runtime.h>
#include <cuda.h>
#include <cuda_bf16.h>
#include <cstdint>

#define N_PTS 6000
#define N_TRI 16000
#define N_MOV 4000
#define N_BND 1500
#define BATCH 16
#define EPSF 1e-8f

// GEMM tiling: C[m=4000,n=16] = Vf[m,k=16000] * D[k,16]
#define CK 64                 // k per iteration
#define NCHUNK (N_TRI / CK)   // 250
#define KS 9                  // k-splits: grid 32 x 9 = 288 blocks, 2 CTA/SM -> 1 wave
#define MTILES 32             // 32 * 128 m-rows

// smem per stage: A = 2 halves x (128 rows x 128B, SW128) ; B = 32 rows x 128B, SW128
#define A_HALF 16384
#define A_STAGE (2 * A_HALF)                 // 32768
#define B_STAGE 4096
#define STAGE_SZ (A_STAGE + B_STAGE)         // 36864
#define NSTAGE 2
#define SMEM_BYTES (NSTAGE * STAGE_SZ)       // 73728  -> 2 CTAs/SM
#define STAGE_TX STAGE_SZ                    // TMA delivers full boxes

// ------------------------- device scratch -------------------------
__device__ double g_volc;
__device__ double g_vol[BATCH];
__device__ int    g_owner1[N_PTS];
__device__ int    g_owner2[N_PTS];
__device__ float  g_pz[BATCH * N_PTS * 3];
__device__ __align__(256) __nv_bfloat16 g_dsp[32 * N_TRI];  // rows 0-15 hi[b], 16-31 lo[b]
__device__ float  g_cpart[KS * 4096 * 16];   // [ks][m pad 4096][b]
__device__ float  g_c[BATCH * N_MOV];

// ------------------------- small kernels -------------------------
__global__ void k_init() {
    int i = blockIdx.x * 256 + threadIdx.x;
    if (i < N_PTS) { g_owner1[i] = -1; g_owner2[i] = -1; }
    if (i == 0) g_volc = 0.0;
    if (i < BATCH) g_vol[i] = 0.0;
}

__global__ void k_owners(const int* __restrict__ idx1, const int* __restrict__ idx2) {
    int i = blockIdx.x * 256 + threadIdx.x;
    if (i < N_MOV) atomicMax(&g_owner1[idx1[i]], i);
    if (i < N_BND) atomicMax(&g_owner2[idx2[i]], i);
}

__global__ void k_build(const float* __restrict__ x, const float* __restrict__ y,
                        const float* __restrict__ pz0, float* __restrict__ out) {
    int i = blockIdx.x * 256 + threadIdx.x;
    if (i < BATCH * N_PTS) {
        int b = i / N_PTS, p = i - b * N_PTS;
        float cx = pz0[p * 3 + 0], cy = pz0[p * 3 + 1], cz = pz0[p * 3 + 2];
        int o2 = g_owner2[p];
        if (o2 >= 0) {
            cx = y[b * (2 * N_BND) + o2 * 2 + 0];
            cz = y[b * (2 * N_BND) + o2 * 2 + 1];
        }
        int o1 = g_owner1[p];
        if (o1 >= 0) {
            cx = x[(b * N_MOV + o1) * 3 + 0];
            cy = x[(b * N_MOV + o1) * 3 + 1];
            cz = x[(b * N_MOV + o1) * 3 + 2];
        }
        g_pz[i * 3 + 0] = cx; g_pz[i * 3 + 1] = cy; g_pz[i * 3 + 2] = cz;
    }
    int stride = gridDim.x * 256;
    for (int j = i; j < BATCH * N_MOV * 3; j += stride) out[j] = x[j];
}

__global__ void k_vol(const float* __restrict__ pz0, const int* __restrict__ tri) {
    __shared__ double sred[256];
    int t = blockIdx.x * 256 + threadIdx.x;
    int b = blockIdx.y;
    const float* P = (b < BATCH) ? (g_pz + (size_t)b * N_PTS * 3) : pz0;
    double contrib = 0.0;
    if (t < N_TRI) {
        int p0 = tri[3 * t + 0] * 3, p1 = tri[3 * t + 1] * 3, p2 = tri[3 * t + 2] * 3;
        float x0 = P[p0], y0 = P[p0 + 1], z0 = P[p0 + 2];
        float x1 = P[p1], y1 = P[p1 + 1], z1 = P[p1 + 2];
        float x2 = P[p2], y2 = P[p2 + 1], z2 = P[p2 + 2];
        float det = (y1 - y0) * (z2 - z0) - (z1 - z0) * (y2 - y0);
        contrib = (double)((x0 + x1 + x2) * (det * (1.0f / 6.0f)));
    }
    sred[threadIdx.x] = contrib;
    __syncthreads();
    for (int o = 128; o > 0; o >>= 1) {
        if (threadIdx.x < o) sred[threadIdx.x] += sred[threadIdx.x + o];
        __syncthreads();
    }
    if (threadIdx.x == 0) {
        if (b < BATCH) atomicAdd(&g_vol[b], sred[0]);
        else           atomicAdd(&g_volc, sred[0]);
    }
}

// dets -> bf16 hi/lo planes g_dsp[b][t] (hi) and g_dsp[16+b][t] (lo)
template <int AXIS>
__global__ void k_det(const int* __restrict__ tri) {
    int i = blockIdx.x * 256 + threadIdx.x;
    if (i >= BATCH * N_TRI) return;
    int b = i / N_TRI;
    int t = i - b * N_TRI;
    int p0 = tri[3 * t + 0] * 3, p1 = tri[3 * t + 1] * 3, p2 = tri[3 * t + 2] * 3;
    const float* P = g_pz + (size_t)b * N_PTS * 3;
    float det;
    if (AXIS == 2) {       // coeff_z: (x,y), pivot vertex 2
        float x0 = P[p0], y0 = P[p0 + 1], x1 = P[p1], y1 = P[p1 + 1], x2 = P[p2], y2 = P[p2 + 1];
        det = (x0 - x2) * (y1 - y2) - (y0 - y2) * (x1 - x2);
    } else if (AXIS == 1) { // coeff_y: (x,z), pivot vertex 1
        float x0 = P[p0], z0 = P[p0 + 2], x1 = P[p1], z1 = P[p1 + 2], x2 = P[p2], z2 = P[p2 + 2];
        det = (x0 - x1) * (z2 - z1) - (z0 - z1) * (x2 - x1);
    } else {               // coeff_x: (y,z), pivot vertex 0
        float y0 = P[p0 + 1], z0 = P[p0 + 2], y1 = P[p1 + 1], z1 = P[p1 + 2], y2 = P[p2 + 1], z2 = P[p2 + 2];
        det = (y1 - y0) * (z2 - z0) - (z1 - z0) * (y2 - y0);
    }
    float v = det * (1.0f / 6.0f);
    __nv_bfloat16 h = __float2bfloat16_rn(v);
    __nv_bfloat16 l = __float2bfloat16_rn(v - __bfloat162float(h));
    g_dsp[b * N_TRI + t] = h;
    g_dsp[(16 + b) * N_TRI + t] = l;
}

// ------------------------- helpers -------------------------
__device__ __forceinline__ uint32_t smem_u32(const void* p) {
    return (uint32_t)__cvta_generic_to_shared(p);
}
__device__ __forceinline__ void tma2d(uint32_t dst, const CUtensorMap* m, int x, int y, uint32_t mbar) {
    asm volatile(
        "cp.async.bulk.tensor.2d.shared::cta.global.tile.mbarrier::complete_tx::bytes "
        "[%0], [%1, {%2, %3}], [%4];"
        :: "r"(dst), "l"(m), "r"(x), "r"(y), "r"(mbar) : "memory");
}
__device__ __forceinline__ void mbar_wait(uint32_t addr, uint32_t parity) {
    asm volatile(
        "{\n\t.reg .pred P;\n\t"
        "W%=:\n\tmbarrier.try_wait.parity.acquire.cta.shared::cta.b64 P, [%0], %1;\n\t"
        "@!P bra W%=;\n\t}"
        :: "r"(addr), "r"(parity) : "memory");
}
// split float2 -> (hi bf16x2, lo bf16x2); low half = first element
__device__ __forceinline__ void bsplit(float a0, float a1, uint32_t& h, uint32_t& l) {
    asm("cvt.rn.bf16x2.f32 %0, %1, %2;" : "=r"(h) : "f"(a1), "f"(a0));
    float h0 = __uint_as_float(h << 16);
    float h1 = __uint_as_float(h & 0xffff0000u);
    asm("cvt.rn.bf16x2.f32 %0, %1, %2;" : "=r"(l) : "f"(a1 - h1), "f"(a0 - h0));
}
#define MMA16816(C0,C1,C2,C3,A0,A1,A2,A3,B0,B1) \
    asm("mma.sync.aligned.m16n8k16.row.col.f32.bf16.bf16.f32 " \
        "{%0,%1,%2,%3},{%4,%5,%6,%7},{%8,%9},{%0,%1,%2,%3};" \
        : "+f"(C0), "+f"(C1), "+f"(C2), "+f"(C3) \
        : "r"(A0), "r"(A1), "r"(A2), "r"(A3), "r"(B0), "r"(B1))

// ------------------------- GEMM: warp MMA, TMA tensor loads, 2-stage -------------------------
__global__ void __launch_bounds__(256) k_gemm(const __grid_constant__ CUtensorMap tmA,
                                              const __grid_constant__ CUtensorMap tmB) {
    extern __shared__ __align__(1024) char sm[];
    __shared__ __align__(8) unsigned long long s_mbar[NSTAGE];

    const int tid  = threadIdx.x;
    const int lane = tid & 31;
    const int w    = tid >> 5;
    const int g    = lane >> 2;     // 0..7
    const int tig  = lane & 3;      // 0..3
    const int mbase = blockIdx.x * 128;
    const int ksid  = blockIdx.y;
    const int c0 = (NCHUNK * ksid) / KS;
    const int c1 = (NCHUNK * (ksid + 1)) / KS;

    uint32_t mb[NSTAGE];
#pragma unroll
    for (int s = 0; s < NSTAGE; s++) mb[s] = smem_u32(&s_mbar[s]);
    if (tid == 0) {
#pragma unroll
        for (int s = 0; s < NSTAGE; s++)
            asm volatile("mbarrier.init.shared.b64 [%0], 1;" :: "r"(mb[s]) : "memory");
        asm volatile("fence.proxy.async.shared::cta;" ::: "memory");
    }
    __syncthreads();

    const uint32_t sbase = smem_u32(sm);

    auto issue = [&](int st, int it) {
        if (tid == 0) {
            const int t0 = it * CK;
            asm volatile("mbarrier.arrive.expect_tx.shared.b64 _, [%0], %1;"
                         :: "r"(mb[st]), "r"((uint32_t)STAGE_TX) : "memory");
            tma2d(sbase + st * STAGE_SZ,              &tmA, t0,      mbase, mb[st]);
            tma2d(sbase + st * STAGE_SZ + A_HALF,     &tmA, t0 + 32, mbase, mb[st]);
            tma2d(sbase + st * STAGE_SZ + A_STAGE,    &tmB, t0,      0,     mb[st]);
        }
    };

    const int niter = c1 - c0;
    issue(0, c0);
    if (niter > 1) issue(1, c0 + 1);

    float acc[2][4];
#pragma unroll
    for (int nt = 0; nt < 2; nt++)
#pragma unroll
        for (int q = 0; q < 4; q++) acc[nt][q] = 0.f;

    int phase[NSTAGE] = { 0, 0 };

    const int swz = g << 4;          // SW128 XOR for rows r with r&7 == g

    for (int li = 0; li < niter; ++li) {
        const int st = li & 1;
        mbar_wait(mb[st], phase[st]);
        phase[st] ^= 1;

        const char* S = sm + st * STAGE_SZ;
        const char* Brow = S + A_STAGE + g * 128;   // rows g, 8+g, 16+g, 24+g share swz

#pragma unroll
        for (int ks = 0; ks < 4; ks++) {
            const char* Ah = S + (ks >> 1) * A_HALF + (w * 16 + g) * 128;
            const int cb = (ks & 1) * 64 + tig * 8;
            float2 x00 = *reinterpret_cast<const float2*>(Ah + ((cb)      ^ swz));
            float2 x01 = *reinterpret_cast<const float2*>(Ah + ((cb + 32) ^ swz));
            float2 x10 = *reinterpret_cast<const float2*>(Ah + 1024 + ((cb)      ^ swz));
            float2 x11 = *reinterpret_cast<const float2*>(Ah + 1024 + ((cb + 32) ^ swz));
            uint32_t ah0, al0, ah1, al1, ah2, al2, ah3, al3;
            bsplit(x00.x, x00.y, ah0, al0);
            bsplit(x10.x, x10.y, ah1, al1);
            bsplit(x01.x, x01.y, ah2, al2);
            bsplit(x11.x, x11.y, ah3, al3);

            const int kb = ks * 32 + tig * 4;
            uint32_t bh0a = *reinterpret_cast<const uint32_t*>(Brow + ((kb)      ^ swz));
            uint32_t bh0b = *reinterpret_cast<const uint32_t*>(Brow + ((kb + 16) ^ swz));
            uint32_t bh1a = *reinterpret_cast<const uint32_t*>(Brow + 8 * 128  + ((kb)      ^ swz));
            uint32_t bh1b = *reinterpret_cast<const uint32_t*>(Brow + 8 * 128  + ((kb + 16) ^ swz));
            uint32_t bl0a = *reinterpret_cast<const uint32_t*>(Brow + 16 * 128 + ((kb)      ^ swz));
            uint32_t bl0b = *reinterpret_cast<const uint32_t*>(Brow + 16 * 128 + ((kb + 16) ^ swz));
            uint32_t bl1a = *reinterpret_cast<const uint32_t*>(Brow + 24 * 128 + ((kb)      ^ swz));
            uint32_t bl1b = *reinterpret_cast<const uint32_t*>(Brow + 24 * 128 + ((kb + 16) ^ swz));

            MMA16816(acc[0][0], acc[0][1], acc[0][2], acc[0][3], ah0, ah1, ah2, ah3, bh0a, bh0b);
            MMA16816(acc[0][0], acc[0][1], acc[0][2], acc[0][3], ah0, ah1, ah2, ah3, bl0a, bl0b);
            MMA16816(acc[0][0], acc[0][1], acc[0][2], acc[0][3], al0, al1, al2, al3, bh0a, bh0b);
            MMA16816(acc[1][0], acc[1][1], acc[1][2], acc[1][3], ah0, ah1, ah2, ah3, bh1a, bh1b);
            MMA16816(acc[1][0], acc[1][1], acc[1][2], acc[1][3], ah0, ah1, ah2, ah3, bl1a, bl1b);
            MMA16816(acc[1][0], acc[1][1], acc[1][2], acc[1][3], al0, al1, al2, al3, bh1a, bh1b);
        }

        __syncthreads();                 // all warps done reading stage st
        if (li + NSTAGE < niter) issue(st, c0 + li + NSTAGE);
    }

    // epilogue: d0,d1 -> (row g, cols 2*tig, 2*tig+1); d2,d3 -> row g+8
    const int m0 = mbase + w * 16 + g;
    const int m1 = m0 + 8;
#pragma unroll
    for (int nt = 0; nt < 2; nt++) {
        const int n0 = nt * 8 + tig * 2;
        if (m0 < N_MOV)
            *reinterpret_cast<float2*>(&g_cpart[((size_t)ksid * 4096 + m0) * 16 + n0]) =
                make_float2(acc[nt][0], acc[nt][1]);
        if (m1 < N_MOV)
            *reinterpret_cast<float2*>(&g_cpart[((size_t)ksid * 4096 + m1) * 16 + n0]) =
                make_float2(acc[nt][2], acc[nt][3]);
    }
}

// ------------------------- fused: finalize c, scale, update pts & pz -------------------------
__global__ void k_scale_update(const int* __restrict__ idx1, float* __restrict__ out, int axis) {
    __shared__ float red[256];
    __shared__ float s_scale;
    int b = blockIdx.x;
    int tid = threadIdx.x;
    float sq = 0.f;
    for (int m = tid; m < N_MOV; m += 256) {
        float cv = 0.f;
#pragma unroll
        for (int sp = 0; sp < KS; sp++)
            cv += g_cpart[((size_t)sp * 4096 + m) * 16 + b];
        g_c[b * N_MOV + m] = cv;
        sq += cv * cv;
    }
    red[tid] = sq;
    __syncthreads();
    for (int o = 128; o > 0; o >>= 1) {
        if (tid < o) red[tid] += red[tid + o];
        __syncthreads();
    }
    if (tid == 0) {
        float a = (float)((g_volc - g_vol[b]) / 3.0);
        s_scale = a / (red[0] + EPSF);
    }
    __syncthreads();
    const float s = s_scale;
    for (int m = tid; m < N_MOV; m += 256) {
        int i = b * N_MOV + m;
        float nv = out[i * 3 + axis] + g_c[i] * s;
        out[i * 3 + axis] = nv;
        int p = idx1[m];
        if (g_owner1[p] == m) g_pz[((size_t)b * N_PTS + p) * 3 + axis] = nv;
    }
}

// ------------------------- host -------------------------
typedef CUresult (*EncodeFn)(CUtensorMap*, CUtensorMapDataType, cuuint32_t, void*,
                             const cuuint64_t*, const cuuint64_t*, const cuuint32_t*,
                             const cuuint32_t*, CUtensorMapInterleave, CUtensorMapSwizzle,
                             CUtensorMapL2promotion, CUtensorMapFloatOOBfill);

extern "C" void kernel_launch(void* const* d_in, const int* in_sizes, int n_in,
                              void* d_out, int out_size) {
    const float* x   = (const float*)d_in[0];
    const float* y   = (const float*)d_in[1];
    const float* pz0 = (const float*)d_in[2];
    const float* Vf  = (const float*)d_in[3];
    const int* idx1  = (const int*)d_in[4];
    const int* idx2  = (const int*)d_in[5];
    const int* tri   = (const int*)d_in[6];
    float* out = (float*)d_out;

    cudaFuncSetAttribute(k_gemm, cudaFuncAttributeMaxDynamicSharedMemorySize, SMEM_BYTES);

    EncodeFn enc = nullptr;
    {
        void* p = nullptr;
        cudaDriverEntryPointQueryResult qr;
        cudaGetDriverEntryPoint("cuTensorMapEncodeTiled", &p, cudaEnableDefault, &qr);
        enc = (EncodeFn)p;
    }

    void* dsp_ptr = nullptr;
    cudaGetSymbolAddress(&dsp_ptr, g_dsp);

    CUtensorMap tmA, tmB;
    {
        cuuint64_t dims[2]    = { (cuuint64_t)N_TRI, (cuuint64_t)N_MOV };
        cuuint64_t strides[1] = { (cuuint64_t)N_TRI * 4 };
        cuuint32_t box[2]     = { 32, 128 };
        cuuint32_t es[2]      = { 1, 1 };
        enc(&tmA, CU_TENSOR_MAP_DATA_TYPE_FLOAT32, 2, (void*)Vf,
            dims, strides, box, es,
            CU_TENSOR_MAP_INTERLEAVE_NONE, CU_TENSOR_MAP_SWIZZLE_128B,
            CU_TENSOR_MAP_L2_PROMOTION_L2_128B, CU_TENSOR_MAP_FLOAT_OOB_FILL_NONE);
    }
    {
        cuuint64_t dims[2]    = { (cuuint64_t)N_TRI, 32 };
        cuuint64_t strides[1] = { (cuuint64_t)N_TRI * 2 };
        cuuint32_t box[2]     = { 64, 32 };
        cuuint32_t es[2]      = { 1, 1 };
        enc(&tmB, CU_TENSOR_MAP_DATA_TYPE_BFLOAT16, 2, dsp_ptr,
            dims, strides, box, es,
            CU_TENSOR_MAP_INTERLEAVE_NONE, CU_TENSOR_MAP_SWIZZLE_128B,
            CU_TENSOR_MAP_L2_PROMOTION_L2_128B, CU_TENSOR_MAP_FLOAT_OOB_FILL_NONE);
    }

    k_init<<<24, 256>>>();
    k_owners<<<16, 256>>>(idx1, idx2);
    k_build<<<375, 256>>>(x, y, pz0, out);
    k_vol<<<dim3(63, BATCH + 1), 256>>>(pz0, tri);

    k_det<2><<<1000, 256>>>(tri);
    k_gemm<<<dim3(MTILES, KS), 256, SMEM_BYTES>>>(tmA, tmB);
    k_scale_update<<<BATCH, 256>>>(idx1, out, 2);

    k_det<1><<<1000, 256>>>(tri);
    k_gemm<<<dim3(MTILES, KS), 256, SMEM_BYTES>>>(tmA, tmB);
    k_scale_update<<<BATCH, 256>>>(idx1, out, 1);

    k_det<0><<<1000, 256>>>(tri);
    k_gemm<<<dim3(MTILES, KS), 256, SMEM_BYTES>>>(tmA, tmB);
    k_scale_update<<<BATCH, 256>>>(idx1, out, 0);
}